// round 14
// baseline (speedup 1.0000x reference)
#include <cuda_runtime.h>
#include <cuda_fp16.h>
#include <mma.h>
#include <cstdint>

using namespace nvcuda;

#define NN 50000
#define NNP 50048              // 391 * 128, padded rows (zero-filled in g_xh)
#define NE 800000
#define FD 256
#define NB 196                 // (NN + 255) / 256 scan blocks

// ---------------- device scratch (no allocations allowed) ----------------
__device__ float  g_dis[NN];
__device__ int    g_cnt[NN];
__device__ int    g_off[NN];
__device__ int    g_cur[NN];
__device__ int    g_col[NE];
__device__ float  g_w[NE];
__device__ __half g_xh[(size_t)NNP * FD];  // x in fp16 (RN), padded rows = 0
__device__ __half g_wh[FD * FD];           // W in fp16 (RN)
__device__ __half g_yh[(size_t)NNP * FD];  // y = x @ W^T in fp16
__device__ int    g_blk[NB];
__device__ int    g_blkoff[NB];
__device__ int    g_is64;

// load 4 consecutive edge indices (vectorized for both dtypes)
__device__ __forceinline__ void load4idx(const void* ei, long long base, int r[4]) {
    if (g_is64) {
        longlong2 a = *(const longlong2*)((const long long*)ei + base);
        longlong2 b = *(const longlong2*)((const long long*)ei + base + 2);
        r[0] = (int)a.x; r[1] = (int)a.y; r[2] = (int)b.x; r[3] = (int)b.y;
    } else {
        int4 a = *(const int4*)((const int*)ei + base);
        r[0] = a.x; r[1] = a.y; r[2] = a.z; r[3] = a.w;
    }
}

// ---------------- cp.async helpers ----------------
__device__ __forceinline__ uint32_t smem_u32(const void* p) {
    uint32_t a;
    asm("{ .reg .u64 t; cvta.to.shared.u64 t, %1; cvt.u32.u64 %0, t; }" : "=r"(a) : "l"(p));
    return a;
}
__device__ __forceinline__ void cp_async16(uint32_t dst, const void* src) {
    asm volatile("cp.async.cg.shared.global [%0], [%1], 16;"
                 :: "r"(dst), "l"(src) : "memory");
}
#define CP_COMMIT() asm volatile("cp.async.commit_group;" ::: "memory")
#define CP_WAIT1()  asm volatile("cp.async.wait_group 1;" ::: "memory")
#define CP_WAIT0()  asm volatile("cp.async.wait_group 0;" ::: "memory")

// L1-bypassing 16B gather
__device__ __forceinline__ uint4 ldcg16(const void* p) {
    uint4 q;
    asm volatile("ld.global.cg.v4.u32 {%0,%1,%2,%3}, [%4];"
                 : "=r"(q.x), "=r"(q.y), "=r"(q.z), "=r"(q.w) : "l"(p));
    return q;
}

// ---------------- fp32 -> fp16 RN conversions ----------------
__global__ __launch_bounds__(256) void k_xhalf(const float* __restrict__ x) {
    long long idx = (long long)blockIdx.x * blockDim.x + threadIdx.x;
    const long long total = (long long)NNP * FD / 8;
    if (idx >= total) return;
    size_t base = (size_t)idx * 8;
    int row = (int)(base >> 8);
    __align__(16) __half2 h[4];
    if (row < NN) {
        float4 a = *(const float4*)(x + base);
        float4 b = *(const float4*)(x + base + 4);
        h[0] = __floats2half2_rn(a.x, a.y);
        h[1] = __floats2half2_rn(a.z, a.w);
        h[2] = __floats2half2_rn(b.x, b.y);
        h[3] = __floats2half2_rn(b.z, b.w);
    } else {
        h[0] = h[1] = h[2] = h[3] = __floats2half2_rn(0.f, 0.f);
    }
    *(uint4*)(g_xh + base) = *(const uint4*)h;
}

__global__ __launch_bounds__(256) void k_whalf(const float* __restrict__ W) {
    int idx = blockIdx.x * blockDim.x + threadIdx.x;
    size_t base = (size_t)idx * 8;
    float4 a = *(const float4*)(W + base);
    float4 b = *(const float4*)(W + base + 4);
    __align__(16) __half2 h[4];
    h[0] = __floats2half2_rn(a.x, a.y);
    h[1] = __floats2half2_rn(a.z, a.w);
    h[2] = __floats2half2_rn(b.x, b.y);
    h[3] = __floats2half2_rn(b.z, b.w);
    *(uint4*)(g_wh + base) = *(const uint4*)h;
}

// ---------------- init + dtype detect ----------------
__global__ void k_init(const int* __restrict__ ei32) {
    int i = blockIdx.x * blockDim.x + threadIdx.x;
    if (i < NN) { g_dis[i] = 0.0f; g_cnt[i] = 0; }
    if (blockIdx.x == 0) {
        int nz = 0;
        if (threadIdx.x < 128) nz = (ei32[2 * threadIdx.x + 1] != 0) ? 1 : 0;
        int any = __syncthreads_or(nz);
        if (threadIdx.x == 0) g_is64 = (any == 0) ? 1 : 0;
    }
}

// ---------------- degree accumulation (4 edges / thread) ----------------
__global__ void k_deg(const void* __restrict__ ei, const float* __restrict__ C) {
    long long e0 = ((long long)blockIdx.x * blockDim.x + threadIdx.x) * 4;
    if (e0 >= NE) return;
    int r[4];
    load4idx(ei, e0, r);
    float4 c4 = *(const float4*)(C + e0);
#pragma unroll
    for (int i = 0; i < 4; i++) {
        float cv = (i == 0) ? c4.x : (i == 1) ? c4.y : (i == 2) ? c4.z : c4.w;
        atomicAdd(&g_dis[r[i]], cv);
        atomicAdd(&g_cnt[r[i]], 1);
    }
}

// ---------------- hierarchical scan ----------------
__global__ __launch_bounds__(256) void k_scan1() {
    __shared__ int s[256];
    int t = threadIdx.x;
    int i = blockIdx.x * 256 + t;
    int v = 0;
    if (i < NN) {
        float d = g_dis[i];
        g_dis[i] = (d > 0.0f) ? rsqrtf(d) : 0.0f;
        v = g_cnt[i];
    }
    s[t] = v;
    __syncthreads();
#pragma unroll
    for (int off = 128; off > 0; off >>= 1) {
        if (t < off) s[t] += s[t + off];
        __syncthreads();
    }
    if (t == 0) g_blk[blockIdx.x] = s[0];
}

__global__ __launch_bounds__(256) void k_scan2() {
    __shared__ int s[256];
    int t = threadIdx.x;
    int v = (t < NB) ? g_blk[t] : 0;
    s[t] = v;
    __syncthreads();
#pragma unroll
    for (int off = 1; off < 256; off <<= 1) {
        int u = (t >= off) ? s[t - off] : 0;
        __syncthreads();
        s[t] += u;
        __syncthreads();
    }
    if (t < NB) g_blkoff[t] = s[t] - v;
}

__global__ __launch_bounds__(256) void k_scan3() {
    __shared__ int s[256];
    int t = threadIdx.x;
    int i = blockIdx.x * 256 + t;
    int v = (i < NN) ? g_cnt[i] : 0;
    s[t] = v;
    __syncthreads();
#pragma unroll
    for (int off = 1; off < 256; off <<= 1) {
        int u = (t >= off) ? s[t - off] : 0;
        __syncthreads();
        s[t] += u;
        __syncthreads();
    }
    if (i < NN) {
        int excl = g_blkoff[blockIdx.x] + s[t] - v;
        g_off[i] = excl;
        g_cur[i] = excl;
    }
}

// ---------------- scatter edges into CSR (4 edges / thread) --------------
__global__ void k_scatter(const void* __restrict__ ei, const float* __restrict__ C) {
    long long e0 = ((long long)blockIdx.x * blockDim.x + threadIdx.x) * 4;
    if (e0 >= NE) return;
    int r[4], cl[4];
    load4idx(ei, e0, r);
    load4idx(ei, (long long)NE + e0, cl);
    float4 c4 = *(const float4*)(C + e0);
#pragma unroll
    for (int i = 0; i < 4; i++) {
        float cv = (i == 0) ? c4.x : (i == 1) ? c4.y : (i == 2) ? c4.z : c4.w;
        float w = g_dis[r[i]] * cv * g_dis[cl[i]];
        int p = atomicAdd(&g_cur[r[i]], 1);
        g_col[p] = cl[i];
        g_w[p]   = w;
    }
}

// ---------------- fp16 tensor-core GEMM (both halves, grid.y = 2) -------
#define GM_BM 128
#define GM_BK 32
#define BKPH  40   // padded row (halves); 80B rows

__global__ __launch_bounds__(256, 2) void k_gemm_h() {
    __shared__ __align__(16) __half As[2][GM_BM][BKPH];   // 20 KB
    __shared__ __align__(16) __half Bs[2][GM_BM][BKPH];   // 20 KB

    const int tid  = threadIdx.x;
    const int wid  = tid >> 5;
    const int lane = tid & 31;
    const int wm = wid >> 2;
    const int wn = wid & 3;
    const int bm = blockIdx.x;
    const int n0 = blockIdx.y * 128;

    wmma::fragment<wmma::accumulator, 16, 16, 16, float> acc[4][2];
#pragma unroll
    for (int i = 0; i < 4; i++)
#pragma unroll
        for (int j = 0; j < 2; j++) wmma::fill_fragment(acc[i][j], 0.0f);

    int aR[2], aC[2];
#pragma unroll
    for (int i = 0; i < 2; i++) {
        int f = tid + 256 * i;
        aR[i] = f >> 2;
        aC[i] = (f & 3) * 8;
    }
    const __half* Asrc[2];
    const __half* Bsrc[2];
#pragma unroll
    for (int i = 0; i < 2; i++) {
        Asrc[i] = g_xh + (size_t)(bm * GM_BM + aR[i]) * FD + aC[i];
        Bsrc[i] = g_wh + (size_t)(n0 + aR[i]) * FD + aC[i];
    }

    uint32_t sa[2][2], sb[2][2];
#pragma unroll
    for (int b = 0; b < 2; b++)
#pragma unroll
        for (int i = 0; i < 2; i++) {
            sa[b][i] = smem_u32(&As[b][aR[i]][aC[i]]);
            sb[b][i] = smem_u32(&Bs[b][aR[i]][aC[i]]);
        }

    auto issue = [&](int k, int buf) {
        const int k0 = k * GM_BK;
#pragma unroll
        for (int i = 0; i < 2; i++) {
            cp_async16(sa[buf][i], Asrc[i] + k0);
            cp_async16(sb[buf][i], Bsrc[i] + k0);
        }
        CP_COMMIT();
    };

    issue(0, 0);
    issue(1, 1);
    CP_WAIT1();
    __syncthreads();

    const int NCH = FD / GM_BK; // 8
    for (int c = 0; c < NCH; c++) {
        const int p = c & 1;

#pragma unroll
        for (int ks = 0; ks < 2; ks++) {
            const int k0 = ks * 16;
            wmma::fragment<wmma::matrix_a, 16, 16, 16, __half, wmma::row_major> af[4];
            wmma::fragment<wmma::matrix_b, 16, 16, 16, __half, wmma::col_major> bf[2];
#pragma unroll
            for (int i = 0; i < 4; i++)
                wmma::load_matrix_sync(af[i], &As[p][wm * 64 + i * 16][k0], BKPH);
#pragma unroll
            for (int j = 0; j < 2; j++)
                wmma::load_matrix_sync(bf[j], &Bs[p][wn * 32 + j * 16][k0], BKPH);
#pragma unroll
            for (int i = 0; i < 4; i++)
#pragma unroll
                for (int j = 0; j < 2; j++)
                    wmma::mma_sync(acc[i][j], af[i], bf[j], acc[i][j]);
        }

        if (c < NCH - 2) {
            __syncthreads();
            issue(c + 2, p);
            CP_WAIT1();
            __syncthreads();
        } else if (c == NCH - 2) {
            CP_WAIT0();
            __syncthreads();
        }
    }

    // fp16 epilogue via smem staging
    __syncthreads();
    float* stage = (float*)&As[0][0][0] + wid * 336;
    const int srow = lane >> 1;
    const int scol = (lane & 1) * 8;
#pragma unroll
    for (int i = 0; i < 4; i++) {
#pragma unroll
        for (int j = 0; j < 2; j++) {
            wmma::store_matrix_sync(stage, acc[i][j], 20, wmma::mem_row_major);
            __syncwarp();
            const float* sp = stage + srow * 20 + scol;
            __align__(16) __half2 h[4];
            h[0] = __floats2half2_rn(sp[0], sp[1]);
            h[1] = __floats2half2_rn(sp[2], sp[3]);
            h[2] = __floats2half2_rn(sp[4], sp[5]);
            h[3] = __floats2half2_rn(sp[6], sp[7]);
            int gr = bm * GM_BM + wm * 64 + i * 16 + srow;
            int gc = n0 + wn * 32 + j * 16 + scol;
            *(uint4*)(g_yh + (size_t)gr * FD + gc) = *(const uint4*)h;
            __syncwarp();
        }
    }
}

// ---------------- full-width SpMM: warp per row, uint4 cg-gather ---------
__device__ __forceinline__ void fma8(float a[8], float w, const uint4& q) {
    const __half2* h = (const __half2*)&q;
#pragma unroll
    for (int k = 0; k < 4; k++) {
        float2 f = __half22float2(h[k]);
        a[2 * k]     = fmaf(w, f.x, a[2 * k]);
        a[2 * k + 1] = fmaf(w, f.y, a[2 * k + 1]);
    }
}

__global__ __launch_bounds__(256) void k_spmm(const float* __restrict__ bias,
                                              float* __restrict__ out) {
    int gwarp = (blockIdx.x * blockDim.x + threadIdx.x) >> 5;
    int lane  = threadIdx.x & 31;
    if (gwarp >= NN) return;

    const int beg = g_off[gwarp];
    const int end = beg + g_cnt[gwarp];
    const int fc  = lane * 8;           // 8 halves = 16 B per lane

    float a[8];
    float4 b0 = *(const float4*)(bias + fc);
    float4 b1 = *(const float4*)(bias + fc + 4);
    a[0] = b0.x; a[1] = b0.y; a[2] = b0.z; a[3] = b0.w;
    a[4] = b1.x; a[5] = b1.y; a[6] = b1.z; a[7] = b1.w;

    int p = beg;
    for (; p + 3 < end; p += 4) {
        int   c0 = g_col[p],     c1 = g_col[p + 1];
        int   c2 = g_col[p + 2], c3 = g_col[p + 3];
        float w0 = g_w[p],       w1 = g_w[p + 1];
        float w2 = g_w[p + 2],   w3 = g_w[p + 3];
        uint4 q0 = ldcg16(g_yh + (size_t)c0 * FD + fc);
        uint4 q1 = ldcg16(g_yh + (size_t)c1 * FD + fc);
        uint4 q2 = ldcg16(g_yh + (size_t)c2 * FD + fc);
        uint4 q3 = ldcg16(g_yh + (size_t)c3 * FD + fc);
        fma8(a, w0, q0);
        fma8(a, w1, q1);
        fma8(a, w2, q2);
        fma8(a, w3, q3);
    }
    for (; p < end; p++) {
        uint4 q = ldcg16(g_yh + (size_t)g_col[p] * FD + fc);
        fma8(a, g_w[p], q);
    }

    float* o = out + (size_t)gwarp * FD + fc;
    *(float4*)(o)     = make_float4(a[0], a[1], a[2], a[3]);
    *(float4*)(o + 4) = make_float4(a[4], a[5], a[6], a[7]);
}

// ---------------- launch ----------------
extern "C" void kernel_launch(void* const* d_in, const int* in_sizes, int n_in,
                              void* d_out, int out_size) {
    const float* x  = (const float*)d_in[0];
    const void*  ei = d_in[1];
    const float* C  = (const float*)d_in[2];
    const float* W  = (const float*)d_in[3];
    const float* b  = (const float*)d_in[4];
    float* out = (float*)d_out;

    cudaStream_t s2;
    cudaStreamCreateWithFlags(&s2, cudaStreamNonBlocking);
    cudaEvent_t eFork, eG;
    cudaEventCreateWithFlags(&eFork, cudaEventDisableTiming);
    cudaEventCreateWithFlags(&eG, cudaEventDisableTiming);

    const int xBlocks = (int)(((long long)NNP * FD / 8 + 255) / 256);
    const int eBlocks = (int)((NE / 4 + 255) / 256);

    // fork: conversions + single GEMM (both halves) on side stream
    cudaEventRecord(eFork, 0);
    cudaStreamWaitEvent(s2, eFork, 0);
    k_whalf<<<FD * FD / 8 / 256, 256, 0, s2>>>(W);
    k_xhalf<<<xBlocks, 256, 0, s2>>>(x);
    dim3 gg(NNP / GM_BM, 2);
    k_gemm_h<<<gg, 256, 0, s2>>>();
    cudaEventRecord(eG, s2);

    // CSR build on default stream (hidden under cvt+GEMM)
    k_init<<<(NN + 255) / 256, 256>>>((const int*)ei);
    k_deg<<<eBlocks, 256>>>(ei, C);
    k_scan1<<<NB, 256>>>();
    k_scan2<<<1, 256>>>();
    k_scan3<<<NB, 256>>>();
    k_scatter<<<eBlocks, 256>>>(ei, C);

    // full-width SpMM after CSR (in-order) + GEMM (event)
    cudaStreamWaitEvent(0, eG, 0);
    k_spmm<<<(NN * 32 + 255) / 256, 256>>>(b, out);
}